// round 7
// baseline (speedup 1.0000x reference)
#include <cuda_runtime.h>
#include <cstdint>

// Problem constants (fixed by setup_inputs)
#define BT 4
#define NV 20000
#define NF 40000
#define HH 256
#define WW 256
#define SS 2048
#define VCAP 20480            // NV padded; = VS * VPB
#define VS 16                 // vert splits
#define SG 8                  // sample groups (256 samples each, 8/lane)
#define VPB (VCAP / VS)       // 1280 verts per block = one tile
#define GRID (VS * BT * SG)   // 512 blocks
#define MASK_PENALTY 1000.0f
#define BIGW 3.0e37f

typedef unsigned long long u64;

// Scratch (no dynamic allocation allowed)
__device__ unsigned char g_visible[BT * NV];
__device__ u64           g_vert8[(size_t)BT * VCAP * 4];  // {x,x},{y,y},{z,z},{w,w}
__device__ int           g_hasInv[BT];
__device__ int           g_min[BT * SS];                  // encoded float mins
__device__ int           g_done = 0;

// ---- packed f32x2 helpers (sm_103a) ----
__device__ __forceinline__ u64 pack2(float lo, float hi) {
    u64 r; asm("mov.b64 %0, {%1, %2};" : "=l"(r) : "f"(lo), "f"(hi)); return r;
}
__device__ __forceinline__ u64 fma2(u64 a, u64 b, u64 c) {
    u64 d; asm("fma.rn.f32x2 %0, %1, %2, %3;" : "=l"(d) : "l"(a), "l"(b), "l"(c)); return d;
}
// order-preserving float -> signed int map (involution)
__device__ __forceinline__ int enc(float f) {
    int k = __float_as_int(f);
    return k >= 0 ? k : (k ^ 0x7FFFFFFF);
}

// ---------------------------------------------------------------------------
// K1: clear visibility flags, hasInv flags, g_done
// ---------------------------------------------------------------------------
__global__ void k_clear() {
    int i = blockIdx.x * blockDim.x + threadIdx.x;
    uint32_t* p = (uint32_t*)g_visible;          // BT*NV bytes = 20000 words
    if (i < (BT * NV) / 4) p[i] = 0u;
    if (i < BT) g_hasInv[i] = 0;
    if (i == 0) g_done = 0;
}

// ---------------------------------------------------------------------------
// K2: visibility scatter (faces / pix_to_face are int32 in memory)
// ---------------------------------------------------------------------------
__global__ void k_vis(const int* __restrict__ p2f,
                      const int* __restrict__ faces) {
    int p = blockIdx.x * blockDim.x + threadIdx.x;
    if (p >= BT * HH * WW) return;
    int fi = p2f[p];
    if ((unsigned)fi >= (unsigned)(BT * NF)) return;   // also rejects -1
    int b  = fi / NF;
    const int* fr = faces + fi * 3;
    int base = b * NV;
    int v0 = fr[0], v1 = fr[1], v2 = fr[2];
    if ((unsigned)v0 < (unsigned)NV) g_visible[base + v0] = 1;
    if ((unsigned)v1 < (unsigned)NV) g_visible[base + v1] = 1;
    if ((unsigned)v2 < (unsigned)NV) g_visible[base + v2] = 1;
}

// ---------------------------------------------------------------------------
// K3: verts -> duplicated packed layout {x,x}{y,y}{z,z}{w,w},
// w = 0.5*|v|^2 if visible else BIGW; padding rows get BIGW.
// Also initializes g_min (independent of visibility).
// ---------------------------------------------------------------------------
__global__ void k_xform(const float* __restrict__ verts) {
    int i = blockIdx.x * blockDim.x + threadIdx.x;
    if (i >= BT * VCAP) return;
    if (i < BT * SS) g_min[i] = enc(BIGW);
    int b = i / VCAP;
    int v = i - b * VCAP;
    float x = 0.f, y = 0.f, z = 0.f, w = BIGW;
    if (v < NV) {
        int idx = (b * NV + v) * 3;
        x = verts[idx + 0]; y = verts[idx + 1]; z = verts[idx + 2];
        bool vis = (g_visible[b * NV + v] != 0);
        if (vis) w = 0.5f * (x * x + y * y + z * z);
        else     g_hasInv[b] = 1;
    }
    u64* o = g_vert8 + (size_t)i * 4;
    o[0] = pack2(x, x); o[1] = pack2(y, y); o[2] = pack2(z, z); o[3] = pack2(w, w);
}

// ---------------------------------------------------------------------------
// K4: main fused min-score kernel (packed f32x2 fma, scalar min on bit-cast
// halves, software-pipelined shared loads) + fused final reduce.
// Grid: 512 blocks = VS(16) x BT(4) x SG(8); 4 blocks/SM -> single wave.
// Block: 256 samples (8/lane as 4 packed pairs) x 1280 verts (one tile).
// ---------------------------------------------------------------------------
__global__ void __launch_bounds__(256, 4)
k_main(const float* __restrict__ bds, float* __restrict__ out) {
    // vert tile (+1 pad vert for branch-free prefetch); reduction buffer
    // overlays the tile (tile is dead after the inner loop's syncthreads).
    __shared__ __align__(16) u64 sv[VPB * 4 + 4];       // 40KB + 32B
    float (*sred)[256] = (float(*)[256])sv;             // 8KB alias

    const int bx   = blockIdx.x;          // 0..511
    const int vs   = bx & 15;
    const int b    = (bx >> 4) & 3;
    const int sg   = bx >> 6;              // 0..7
    const int t    = threadIdx.x;
    const int wid  = t >> 5;
    const int lane = t & 31;

    const float4* bp = ((const float4*)bds) + b * SS + sg * 256;

    u64 nx2[4], ny2[4], nz2[4];
    float mlo[4], mhi[4];
    #pragma unroll
    for (int p = 0; p < 4; p++) {
        float4 sa = bp[lane + 64 * p];         // sample 2p
        float4 sb = bp[lane + 64 * p + 32];    // sample 2p+1
        nx2[p] = pack2(-sa.x, -sb.x);
        ny2[p] = pack2(-sa.y, -sb.y);
        nz2[p] = pack2(-sa.z, -sb.z);
        mlo[p] = BIGW; mhi[p] = BIGW;
    }

    // cooperative tile load: VPB*4 u64 = 2560 uint4, 10 per thread; pad = 0
    {
        const uint4* src = (const uint4*)(g_vert8 + (size_t)(b * VCAP + vs * VPB) * 4);
        uint4* dst = (uint4*)sv;
        #pragma unroll
        for (int j = 0; j < 10; j++)
            dst[t + j * 256] = src[t + j * 256];
        if (t < 2) dst[2560 + t] = make_uint4(0, 0, 0, 0);   // pad vert
    }
    __syncthreads();

    // 160 verts per warp; distance-1 software pipeline of the LDS.128 pair.
    const ulonglong2* wv = ((const ulonglong2*)sv) + wid * 160 * 2;
    ulonglong2 a = wv[0];        // {xx, yy}
    ulonglong2 c = wv[1];        // {zz, ww}
    #pragma unroll 4
    for (int i = 0; i < 160; i++) {
        ulonglong2 an = wv[2 * i + 2];   // prefetch vert i+1 (pad at i=159)
        ulonglong2 cn = wv[2 * i + 3];
        #pragma unroll
        for (int p = 0; p < 4; p++) {
            u64 acc = fma2(a.x, nx2[p], fma2(a.y, ny2[p], fma2(c.x, nz2[p], c.y)));
            float2 f = *reinterpret_cast<float2*>(&acc);   // reg alias, no MOV
            mlo[p] = fminf(mlo[p], f.x);
            mhi[p] = fminf(mhi[p], f.y);
        }
        a = an; c = cn;
    }
    __syncthreads();   // tile dead; sred aliases its space

    #pragma unroll
    for (int p = 0; p < 4; p++) {
        sred[wid][p * 64 + lane]      = mlo[p];
        sred[wid][p * 64 + 32 + lane] = mhi[p];
    }
    __syncthreads();

    // cross-warp min for sample (sg*256 + t), fold into global
    {
        float mm = sred[0][t];
        #pragma unroll
        for (int w = 1; w < 8; w++) mm = fminf(mm, sred[w][t]);
        atomicMin(&g_min[b * SS + sg * 256 + t], enc(mm));
    }

    // ---- last-block final reduction (no separate kernel) ----
    __threadfence();
    __syncthreads();                       // all atomicMins of this block fenced
    if (t == 0)
        sred[0][0] = (atomicAdd(&g_done, 1) == GRID - 1) ? 1.0f : 0.0f;
    __syncthreads();
    if (sred[0][0] == 0.0f) return;

    if (t == 0) g_done = 0;                // reset for next graph replay
    __syncthreads();

    float acc = 0.0f;
    const float4* bq = (const float4*)bds;
    #pragma unroll
    for (int k = 0; k < (BT * SS) / 256; k++) {
        int i = t + k * 256;
        int bb = i >> 11;                  // SS = 2048
        int e = g_min[i];
        float m = __int_as_float(e >= 0 ? e : (e ^ 0x7FFFFFFF));
        float4 sm = bq[i];
        float ss2 = sm.x * sm.x + sm.y * sm.y + sm.z * sm.z;
        float dist = 2.0f * m + ss2;
        if (g_hasInv[bb]) dist = fminf(dist, MASK_PENALTY);
        acc += dist * sm.w;                // sample mask (0/1)
    }
    sred[1][t] = acc;
    __syncthreads();
    #pragma unroll
    for (int s = 128; s > 0; s >>= 1) {
        if (t < s) sred[1][t] += sred[1][t + s];
        __syncthreads();
    }
    if (t == 0) out[0] = sred[1][0] * (1.0f / BT);
}

// ---------------------------------------------------------------------------
// Launch
// Inputs (metadata order): verts f32, bds f32, faces int32, pix_to_face int32,
// n_samples (ignored; fixed = 2048). Output: scalar f32.
// ---------------------------------------------------------------------------
extern "C" void kernel_launch(void* const* d_in, const int* in_sizes, int n_in,
                              void* d_out, int out_size) {
    const float* verts = (const float*)d_in[0];
    const float* bds   = (const float*)d_in[1];
    const int*   faces = (const int*)d_in[2];
    const int*   p2f   = (const int*)d_in[3];
    float* out = (float*)d_out;

    k_clear<<<((BT * NV) / 4 + 255) / 256, 256>>>();
    k_vis<<<(BT * HH * WW + 255) / 256, 256>>>(p2f, faces);
    k_xform<<<(BT * VCAP + 255) / 256, 256>>>(verts);
    k_main<<<GRID, 256>>>(bds, out);
}

// round 8
// speedup vs baseline: 1.0413x; 1.0413x over previous
#include <cuda_runtime.h>
#include <cstdint>

// Problem constants (fixed by setup_inputs)
#define BT 4
#define NV 20000
#define NF 40000
#define HH 256
#define WW 256
#define SS 2048
#define VCAP 20480            // NV padded; = VS * VPB
#define VS 16                 // vert splits
#define SG 16                 // sample groups (128 samples each, 2 pairs/lane)
#define VPB (VCAP / VS)       // 1280 verts per block = one tile
#define GRID (VS * BT * SG)   // 1024 blocks
#define MASK_PENALTY 1000.0f
#define BIGW 3.0e37f

typedef unsigned long long u64;

// Scratch (no dynamic allocation allowed).
// INVARIANT: g_visible is all-zero and g_hasInv all-zero at every
// kernel_launch entry (static zero-init on first call; consumers restore
// zeros after reading). g_done self-resets. Deterministic across replays.
__device__ unsigned char g_visible[BT * NV];
__device__ u64           g_vert8[(size_t)BT * VCAP * 4];  // {x,x},{y,y},{z,z},{w,w}
__device__ int           g_hasInv[BT];
__device__ int           g_min[BT * SS];                  // encoded float mins
__device__ int           g_done = 0;

// ---- packed f32x2 helpers (sm_103a) ----
__device__ __forceinline__ u64 pack2(float lo, float hi) {
    u64 r; asm("mov.b64 %0, {%1, %2};" : "=l"(r) : "f"(lo), "f"(hi)); return r;
}
__device__ __forceinline__ u64 fma2(u64 a, u64 b, u64 c) {
    u64 d; asm("fma.rn.f32x2 %0, %1, %2, %3;" : "=l"(d) : "l"(a), "l"(b), "l"(c)); return d;
}
__device__ __forceinline__ uint32_t smem_addr(const void* p) {
    return (uint32_t)__cvta_generic_to_shared(p);
}
// order-preserving float -> signed int map (involution)
__device__ __forceinline__ int enc(float f) {
    int k = __float_as_int(f);
    return k >= 0 ? k : (k ^ 0x7FFFFFFF);
}

// ---------------------------------------------------------------------------
// K1: visibility scatter (g_visible enters all-zero by invariant).
// faces / pix_to_face are int32 in memory. 4 pixels per thread (int4).
// ---------------------------------------------------------------------------
__global__ void k_vis(const int4* __restrict__ p2f4,
                      const int* __restrict__ faces) {
    int i = blockIdx.x * blockDim.x + threadIdx.x;   // < (BT*HH*WW)/4 = 65536
    int4 q = p2f4[i];
    int f[4] = {q.x, q.y, q.z, q.w};
    #pragma unroll
    for (int j = 0; j < 4; j++) {
        int fi = f[j];
        if ((unsigned)fi >= (unsigned)(BT * NF)) continue;   // rejects -1
        int b = fi / NF;
        const int* fr = faces + fi * 3;
        int base = b * NV;
        int v0 = fr[0], v1 = fr[1], v2 = fr[2];
        if ((unsigned)v0 < (unsigned)NV) g_visible[base + v0] = 1;
        if ((unsigned)v1 < (unsigned)NV) g_visible[base + v1] = 1;
        if ((unsigned)v2 < (unsigned)NV) g_visible[base + v2] = 1;
    }
}

// ---------------------------------------------------------------------------
// K2: verts -> duplicated packed layout {x,x}{y,y}{z,z}{w,w},
// w = 0.5*|v|^2 if visible else BIGW; padding rows get BIGW.
// Restores g_visible to zero (invariant) and initializes g_min.
// ---------------------------------------------------------------------------
__global__ void k_xform(const float* __restrict__ verts) {
    int i = blockIdx.x * blockDim.x + threadIdx.x;
    if (i >= BT * VCAP) return;
    if (i < BT * SS) g_min[i] = enc(BIGW);
    int b = i / VCAP;
    int v = i - b * VCAP;
    float x = 0.f, y = 0.f, z = 0.f, w = BIGW;
    if (v < NV) {
        int idx = (b * NV + v) * 3;
        x = verts[idx + 0]; y = verts[idx + 1]; z = verts[idx + 2];
        bool vis = (g_visible[b * NV + v] != 0);
        g_visible[b * NV + v] = 0;           // restore invariant for next call
        if (vis) w = 0.5f * (x * x + y * y + z * z);
        else     g_hasInv[b] = 1;
    }
    u64* o = g_vert8 + (size_t)i * 4;
    o[0] = pack2(x, x); o[1] = pack2(y, y); o[2] = pack2(z, z); o[3] = pack2(w, w);
}

// ---------------------------------------------------------------------------
// K3: main fused min-score kernel + fused final reduce.
// Grid: 1024 blocks = VS(16) x BT(4) x SG(16); 5 blocks/SM (40 warps/SM).
// Block: 128 samples (2 packed pairs/lane) x 1280 verts (one tile).
// Per vert per lane: 2 LDS.128 + 6 FFMA2 + 4 FMNMX for 4 pair-evals.
// Mins folded into g_min via order-preserving int atomicMin; last block
// finishes the loss and restores g_hasInv to zero.
// ---------------------------------------------------------------------------
__global__ void __launch_bounds__(256, 5)
k_main(const float* __restrict__ bds, float* __restrict__ out) {
    __shared__ __align__(16) u64 sv[VPB * 4];           // 40KB vert tile
    float (*sred)[128] = (float(*)[128])sv;             // 4KB overlay (tile dead)
    float* rbuf = ((float*)sv) + 1024;                  // reduce buffer (no overlap)
    __shared__ float s_flag;

    const int bx   = blockIdx.x;          // 0..1023
    const int vs   = bx & 15;
    const int b    = (bx >> 4) & 3;
    const int sg   = bx >> 6;              // 0..15
    const int t    = threadIdx.x;
    const int wid  = t >> 5;
    const int lane = t & 31;

    const float4* bp = ((const float4*)bds) + b * SS + sg * 128;

    u64 nx0, ny0, nz0, nx1, ny1, nz1;
    float mlo0 = BIGW, mhi0 = BIGW, mlo1 = BIGW, mhi1 = BIGW;
    {
        float4 sa = bp[lane];          // sample 0
        float4 sb = bp[lane + 32];     // sample 1
        nx0 = pack2(-sa.x, -sb.x); ny0 = pack2(-sa.y, -sb.y); nz0 = pack2(-sa.z, -sb.z);
        sa = bp[lane + 64];            // sample 2
        sb = bp[lane + 96];            // sample 3
        nx1 = pack2(-sa.x, -sb.x); ny1 = pack2(-sa.y, -sb.y); nz1 = pack2(-sa.z, -sb.z);
    }

    // cooperative tile load: VPB*4 u64 = 2560 uint4, 10 per thread
    {
        const uint4* src = (const uint4*)(g_vert8 + (size_t)(b * VCAP + vs * VPB) * 4);
        uint4* dst = (uint4*)sv;
        #pragma unroll
        for (int j = 0; j < 10; j++)
            dst[t + j * 256] = src[t + j * 256];
    }
    __syncthreads();

    // 160 verts per warp (R4-style asm-volatile broadcast loads)
    uint32_t addr = smem_addr(sv) + (wid * 160) * 32;
    #pragma unroll 4
    for (int i = 0; i < 160; i++) {
        u64 xx, yy, zz, ww;
        asm volatile("ld.shared.v2.u64 {%0, %1}, [%2];"
                     : "=l"(xx), "=l"(yy) : "r"(addr));
        asm volatile("ld.shared.v2.u64 {%0, %1}, [%2];"
                     : "=l"(zz), "=l"(ww) : "r"(addr + 16));
        u64 acc0 = fma2(xx, nx0, fma2(yy, ny0, fma2(zz, nz0, ww)));
        u64 acc1 = fma2(xx, nx1, fma2(yy, ny1, fma2(zz, nz1, ww)));
        mlo0 = fminf(mlo0, __uint_as_float((unsigned)acc0));
        mhi0 = fminf(mhi0, __uint_as_float((unsigned)(acc0 >> 32)));
        mlo1 = fminf(mlo1, __uint_as_float((unsigned)acc1));
        mhi1 = fminf(mhi1, __uint_as_float((unsigned)(acc1 >> 32)));
        addr += 32;
    }
    __syncthreads();   // tile dead; sred overlays its space

    sred[wid][lane]      = mlo0;
    sred[wid][lane + 32] = mhi0;
    sred[wid][lane + 64] = mlo1;
    sred[wid][lane + 96] = mhi1;
    __syncthreads();

    // cross-warp min for sample (sg*128 + t), fold into global
    if (t < 128) {
        float mm = sred[0][t];
        #pragma unroll
        for (int w = 1; w < 8; w++) mm = fminf(mm, sred[w][t]);
        atomicMin(&g_min[b * SS + sg * 128 + t], enc(mm));
    }

    // ---- last-block final reduction (no separate kernel) ----
    __threadfence();
    __syncthreads();                       // all atomicMins of this block fenced
    if (t == 0)
        s_flag = (atomicAdd(&g_done, 1) == GRID - 1) ? 1.0f : 0.0f;
    __syncthreads();
    if (s_flag == 0.0f) return;

    if (t == 0) g_done = 0;                // reset for next graph replay

    float acc = 0.0f;
    const float4* bq = (const float4*)bds;
    #pragma unroll
    for (int k = 0; k < (BT * SS) / 256; k++) {
        int i = t + k * 256;
        int bb = i >> 11;                  // SS = 2048
        int e = g_min[i];
        float m = __int_as_float(e >= 0 ? e : (e ^ 0x7FFFFFFF));
        float4 sm = bq[i];
        float ss2 = sm.x * sm.x + sm.y * sm.y + sm.z * sm.z;
        float dist = 2.0f * m + ss2;
        if (g_hasInv[bb]) dist = fminf(dist, MASK_PENALTY);
        acc += dist * sm.w;                // sample mask (0/1)
    }
    rbuf[t] = acc;
    __syncthreads();                       // also orders g_hasInv reads below
    if (t < BT) g_hasInv[t] = 0;           // restore invariant for next call
    #pragma unroll
    for (int s = 128; s > 0; s >>= 1) {
        if (t < s) rbuf[t] += rbuf[t + s];
        __syncthreads();
    }
    if (t == 0) out[0] = rbuf[0] * (1.0f / BT);
}

// ---------------------------------------------------------------------------
// Launch
// Inputs (metadata order): verts f32, bds f32, faces int32, pix_to_face int32,
// n_samples (ignored; fixed = 2048). Output: scalar f32.
// ---------------------------------------------------------------------------
extern "C" void kernel_launch(void* const* d_in, const int* in_sizes, int n_in,
                              void* d_out, int out_size) {
    const float* verts = (const float*)d_in[0];
    const float* bds   = (const float*)d_in[1];
    const int*   faces = (const int*)d_in[2];
    const int*   p2f   = (const int*)d_in[3];
    float* out = (float*)d_out;

    k_vis<<<(BT * HH * WW) / 4 / 256, 256>>>((const int4*)p2f, faces);
    k_xform<<<(BT * VCAP + 255) / 256, 256>>>(verts);
    k_main<<<GRID, 256>>>(bds, out);
}